// round 17
// baseline (speedup 1.0000x reference)
#include <cuda_runtime.h>
#include <cuda_bf16.h>

// Inputs (metadata order):
//   d_in[0] encoder   float32 [262144 * 128]
//   d_in[1] logistic  float32 [4*262144 * 128]
//   d_in[2] v_j       int32   [B]
//   d_in[3] path_idx  int32   [B * L]
//   d_in[4] path_sign int32   [B * L]   (0 where masked-out, else +-1)
//   d_in[5] path_mask bool    [B * L]   (unused: sign==0 <=> mask false)
// Output: float32 [B]

__global__ void __launch_bounds__(256) hm_kernel(
    const float* __restrict__ enc,
    const float* __restrict__ logi,
    const int*   __restrict__ vj,
    const int*   __restrict__ pidx,
    const int*   __restrict__ psign,
    float*       __restrict__ out,
    int B, int L)
{
    const unsigned FULL = 0xFFFFFFFFu;
    int warp = (blockIdx.x * blockDim.x + threadIdx.x) >> 5;
    int lane = threadIdx.x & 31;
    if (warp >= B) return;

    // h row: 128 floats, lane holds float4
    long hrow = (long)__ldg(vj + warp) * 128;
    float4 h = __ldg(reinterpret_cast<const float4*>(enc + hrow) + lane);

    // Each lane caches one (idx, sign) pair of this warp's path (L <= 32 fast path)
    float p = 1.0f;

    if (L <= 32) {
        int my_idx = 0, my_sign = 0;
        if (lane < L) {
            my_idx  = __ldg(pidx  + (long)warp * L + lane);
            my_sign = __ldg(psign + (long)warp * L + lane);
        }

        int l = 0;
        // 2-way unrolled mainloop for ILP
        for (; l + 1 < L; l += 2) {
            int i0 = __shfl_sync(FULL, my_idx,  l);
            int s0 = __shfl_sync(FULL, my_sign, l);
            int i1 = __shfl_sync(FULL, my_idx,  l + 1);
            int s1 = __shfl_sync(FULL, my_sign, l + 1);

            float d0 = 0.0f, d1 = 0.0f;
            if (s0) {
                float4 w = __ldg(reinterpret_cast<const float4*>(logi + (long)i0 * 128) + lane);
                d0 = w.x * h.x + w.y * h.y + w.z * h.z + w.w * h.w;
            }
            if (s1) {
                float4 w = __ldg(reinterpret_cast<const float4*>(logi + (long)i1 * 128) + lane);
                d1 = w.x * h.x + w.y * h.y + w.z * h.z + w.w * h.w;
            }
            #pragma unroll
            for (int o = 16; o > 0; o >>= 1) {
                d0 += __shfl_xor_sync(FULL, d0, o);
                d1 += __shfl_xor_sync(FULL, d1, o);
            }
            if (s0) p *= __fdividef(1.0f, 1.0f + __expf(-(float)s0 * d0));
            if (s1) p *= __fdividef(1.0f, 1.0f + __expf(-(float)s1 * d1));
        }
        if (l < L) {
            int i0 = __shfl_sync(FULL, my_idx,  l);
            int s0 = __shfl_sync(FULL, my_sign, l);
            if (s0) {
                float4 w = __ldg(reinterpret_cast<const float4*>(logi + (long)i0 * 128) + lane);
                float d0 = w.x * h.x + w.y * h.y + w.z * h.z + w.w * h.w;
                #pragma unroll
                for (int o = 16; o > 0; o >>= 1) d0 += __shfl_xor_sync(FULL, d0, o);
                p *= __fdividef(1.0f, 1.0f + __expf(-(float)s0 * d0));
            }
        }
    } else {
        // Generic fallback (L > 32): scalar broadcast loads per step
        for (int l = 0; l < L; ++l) {
            int s0 = __ldg(psign + (long)warp * L + l);
            if (s0) {
                int i0 = __ldg(pidx + (long)warp * L + l);
                float4 w = __ldg(reinterpret_cast<const float4*>(logi + (long)i0 * 128) + lane);
                float d0 = w.x * h.x + w.y * h.y + w.z * h.z + w.w * h.w;
                #pragma unroll
                for (int o = 16; o > 0; o >>= 1) d0 += __shfl_xor_sync(FULL, d0, o);
                p *= __fdividef(1.0f, 1.0f + __expf(-(float)s0 * d0));
            }
        }
    }

    if (lane == 0) out[warp] = p;
}

extern "C" void kernel_launch(void* const* d_in, const int* in_sizes, int n_in,
                              void* d_out, int out_size)
{
    const float* enc   = (const float*)d_in[0];
    const float* logi  = (const float*)d_in[1];
    const int*   vj    = (const int*)d_in[2];
    const int*   pidx  = (const int*)d_in[3];
    const int*   psign = (const int*)d_in[4];
    float*       out   = (float*)d_out;

    int B = in_sizes[2];
    int L = in_sizes[3] / B;

    int threads = 256;                    // 8 warps -> 8 batch rows per block
    int blocks  = (B * 32 + threads - 1) / threads;
    hm_kernel<<<blocks, threads>>>(enc, logi, vj, pidx, psign, out, B, L);
}